// round 10
// baseline (speedup 1.0000x reference)
#include <cuda_runtime.h>

#define TT   2048
#define NCTA 128
#define NTH  512

typedef unsigned long long ull;

__device__ __forceinline__ float losum(ull v) {
    float lo, hi; asm("mov.b64 {%0,%1}, %2;" : "=f"(lo), "=f"(hi) : "l"(v));
    return lo + hi;
}
__device__ __forceinline__ ull ff2(ull a, ull b, ull c) {
    ull d; asm("fma.rn.f32x2 %0, %1, %2, %3;" : "=l"(d) : "l"(a), "l"(b), "l"(c));
    return d;
}
__device__ __forceinline__ ull add2(ull a, ull b) {
    ull d; asm("add.rn.f32x2 %0, %1, %2;" : "=l"(d) : "l"(a), "l"(b));
    return d;
}
__device__ __forceinline__ float ex2f(float x){ float y; asm("ex2.approx.f32 %0, %1;" : "=f"(y) : "f"(x)); return y; }
__device__ __forceinline__ float rcpf(float x){ float y; asm("rcp.approx.f32 %0, %1;" : "=f"(y) : "f"(x)); return y; }
__device__ __forceinline__ float sigm(float x){ return rcpf(1.f + ex2f(-1.4426950408889634f * x)); }
__device__ __forceinline__ float tanh_(float x){ float e = ex2f(2.8853900817779268f * x); return 1.f - 2.f * rcpf(e + 1.f); }

// Partial dot, 4 gates x 2 batches over J float4-chunks (this thread's K-half).
// v j-stride = 4 u2 (4 batches per group); w j-stride = 51 u2.
template<int J>
__device__ __forceinline__ void gates_partial(
    const ulonglong2* __restrict__ wt, int gstr,
    const ulonglong2* __restrict__ va, const ulonglong2* __restrict__ vb,
    float* __restrict__ partial)
{
    ull ax[4], ay[4], bx[4], by[4];
#pragma unroll
    for (int g = 0; g < 4; ++g) { ax[g] = 0ULL; ay[g] = 0ULL; bx[g] = 0ULL; by[g] = 0ULL; }
#pragma unroll
    for (int j = 0; j < J; ++j) {
        const ulonglong2 ha = va[j * 4];
        const ulonglong2 hb = vb[j * 4];
#pragma unroll
        for (int g = 0; g < 4; ++g) {
            const ulonglong2 wv = wt[g * gstr + j * 51];
            ax[g] = ff2(wv.x, ha.x, ax[g]);
            ay[g] = ff2(wv.y, ha.y, ay[g]);
            bx[g] = ff2(wv.x, hb.x, bx[g]);
            by[g] = ff2(wv.y, hb.y, by[g]);
        }
    }
#pragma unroll
    for (int g = 0; g < 4; ++g) {
        partial[g * 2 + 0] = losum(add2(ax[g], ay[g]));
        partial[g * 2 + 1] = losum(add2(bx[g], by[g]));
    }
}

__device__ __forceinline__ float lstm_update(const float* __restrict__ partial,
                                             const float* __restrict__ bias4,
                                             unsigned mask, int s, float& cc)
{
    float full[4];
#pragma unroll
    for (int g = 0; g < 4; ++g) {
        float prov = s ? partial[g * 2 + 0] : partial[g * 2 + 1];
        float recv = __shfl_xor_sync(mask, prov, 1);
        float mine = s ? partial[g * 2 + 1] : partial[g * 2 + 0];
        full[g] = mine + recv + bias4[g];
    }
    float gi = sigm(full[0]), gf = sigm(full[1]);
    float gg = tanh_(full[2]), go = sigm(full[3]);
    cc = gf * cc + gi * gg;
    return go * tanh_(cc);
}

// ---- smem map (u2 = 16B units) ----
// W0: [g][s][j<7][k<51]  : 8*357  = 2856 u2 @ 0
// W1: [g][s][j<13][k<51] : 8*663  = 5304 u2 @ 2856
// W2:                      5304 u2 @ 8160
// V (per group, 424 u2)  @ 13464 + grp*424:
//   v0: 2 bufs x 56   (cols: x0,x1,h0(51),pad3; [j][b])
//   v1: in 52 | own 2 x 52
//   v2: in 52 | own 2 x 52
// WL @ 14312 (26 u2), BL @ 14338 (1 u2)
#define SMEM_BYTES (14340 * 16)

__global__ void __launch_bounds__(NTH, 1)
lstm_kernel(const float* __restrict__ inp,  const float* __restrict__ tim,
            const float* __restrict__ Wih0, const float* __restrict__ Whh0,
            const float* __restrict__ bih0, const float* __restrict__ bhh0,
            const float* __restrict__ Wih1, const float* __restrict__ Whh1,
            const float* __restrict__ bih1, const float* __restrict__ bhh1,
            const float* __restrict__ Wih2, const float* __restrict__ Whh2,
            const float* __restrict__ bih2, const float* __restrict__ bhh2,
            const float* __restrict__ Wlin, const float* __restrict__ blin,
            float* __restrict__ out)
{
    extern __shared__ float sm[];
    ulonglong2* smu2 = (ulonglong2*)sm;
    const int tid = threadIdx.x;
    const int gb0 = blockIdx.x * 8;

    // ---- init (all 512 threads) ----
    for (int i = tid; i < 2856 * 4; i += NTH) {           // W0
        int u = i >> 2, e = i & 3;
        int gs = u / 357, rem = u - gs * 357;
        int j = rem / 51, kk = rem - j * 51;
        int g = gs >> 1, s = gs & 1;
        int c = s * 28 + j * 4 + e;
        int r = g * 51 + kk;
        float v = 0.f;
        if (c < 2)       v = Wih0[r * 2 + c];
        else if (c < 53) v = Whh0[r * 51 + (c - 2)];
        sm[i] = v;
    }
    for (int i = tid; i < 5304 * 4; i += NTH) {           // W1, W2
        int u = i >> 2, e = i & 3;
        int gs = u / 663, rem = u - gs * 663;
        int j = rem / 51, kk = rem - j * 51;
        int g = gs >> 1, s = gs & 1;
        int c = s * 52 + j * 4 + e;
        int r = g * 51 + kk;
        float v1 = 0.f, v2 = 0.f;
        if (c < 51)                  { v1 = Wih1[r * 51 + c];        v2 = Wih2[r * 51 + c]; }
        else if (c >= 52 && c < 103) { v1 = Whh1[r * 51 + (c - 52)]; v2 = Whh2[r * 51 + (c - 52)]; }
        sm[2856 * 4 + i] = v1;
        sm[8160 * 4 + i] = v2;
    }
    for (int i = tid; i < 848 * 4; i += NTH) sm[13464 * 4 + i] = 0.f;   // v regions
    for (int i = tid; i < 104; i += NTH) {
        int col = i / 52, kk = i - col * 52;
        sm[14312 * 4 + i] = (kk < 51) ? Wlin[col * 51 + kk] : 0.f;
    }
    if (tid < 2) sm[14338 * 4 + tid] = blin[tid];
    __syncthreads();

    const int grp = tid >> 8;            // 0 / 1
    const int local = tid & 255;
    if ((local >> 5) == 7) return;       // warps 7,15 exit after init

    const int GVf = (13464 + grp * 424) * 4;
    const ulonglong2* gvu = smu2 + 13464 + grp * 424;
    const int bid = grp + 1;             // named barrier id

    // x(t=0) into v0 buffer 0
    if (local >= 212 && local < 220) {
        int idx = local - 212, xb = idx & 3, xsel = idx >> 2;
        const float* src = xsel ? tim : inp;
        sm[GVf + xb * 4 + xsel] = src[(gb0 + grp * 4 + xb) * TT];
    }

    // gemv roles (valid for local < 204)
    const int s = local & 1;
    const int q = (local >> 1) & 1;
    const int k = local >> 2;
    const int b = 2 * q + s;
    const unsigned mask = (local < 192) ? 0xFFFFFFFFu : 0x00000FFFu;

    float bias0[4], bias1[4], bias2[4];
    if (local < 204) {
#pragma unroll
        for (int g = 0; g < 4; ++g) {
            int r = g * 51 + k;
            bias0[g] = bih0[r] + bhh0[r];
            bias1[g] = bih1[r] + bhh1[r];
            bias2[g] = bih2[r] + bhh2[r];
        }
    }
    const ulonglong2* w0t = smu2 + 0    + s * 357 + k;
    const ulonglong2* w1t = smu2 + 2856 + s * 663 + k;
    const ulonglong2* w2t = smu2 + 8160 + s * 663 + k;

    const int c0 = 2 + k;
    const int h0st = GVf + (((c0 >> 2) * 4 + b) * 4) + (c0 & 3);          // + wp*224
    const int kst  = (((k >> 2) * 4 + b) * 4) + (k & 3);
    const int v1in = GVf + 448  + kst;
    const int v1ow = GVf + 656  + kst;                                     // + wp*208
    const int v2in = GVf + 1072 + kst;
    const int v2ow = GVf + 1280 + kst;                                     // + wp*208

    float cc0 = 0.f, cc1 = 0.f, cc2 = 0.f;

#define NB() asm volatile("bar.sync %0, %1;" :: "r"(bid), "r"(224) : "memory")

#define PHASE0(tv) do {                                                     \
    int rp_ = (tv) & 1, wp_ = 1 - rp_;                                      \
    if (local < 204) {                                                      \
        const ulonglong2* va = gvu + rp_ * 56 + s * 28 + 2 * q;             \
        float partial[8];                                                   \
        gates_partial<7>(w0t, 714, va, va + 1, partial);                    \
        float h = lstm_update(partial, bias0, mask, s, cc0);                \
        sm[h0st + wp_ * 224] = h;                                           \
        sm[v1in] = h;                                                       \
    } else if (local < 212) {                                               \
        if ((tv) > 0) {                                                     \
            int idx = local - 204, hb = idx >> 1, col = idx & 1;            \
            float acc = sm[14338 * 4 + col];                                \
            const float* h2 = sm + GVf + 1280 + rp_ * 208;                  \
            _Pragma("unroll 1")                                             \
            for (int kk = 0; kk < 51; ++kk)                                 \
                acc += sm[14312 * 4 + col * 52 + kk]                        \
                     * h2[((kk >> 2) * 4 + hb) * 4 + (kk & 3)];             \
            if (col) acc = (acc > 30.f) ? acc : log1pf(__expf(acc));        \
            out[((gb0 + grp * 4 + hb) * TT + ((tv) - 1)) * 2 + col] = acc;  \
        }                                                                   \
    } else if (local < 220) {                                               \
        if ((tv) + 1 < TT) {                                                \
            int idx = local - 212, xb = idx & 3, xsel = idx >> 2;           \
            const float* src = xsel ? tim : inp;                            \
            float xin = src[(gb0 + grp * 4 + xb) * TT + ((tv) + 1)];        \
            sm[GVf + wp_ * 224 + xb * 4 + xsel] = xin;                      \
        }                                                                   \
    }                                                                       \
} while (0)

#define PHASE1(tv) do {                                                     \
    int rp_ = (tv) & 1, wp_ = 1 - rp_;                                      \
    if (local < 204) {                                                      \
        const ulonglong2* va = s ? (gvu + 164 + rp_ * 52 + 2 * q)           \
                                 : (gvu + 112 + 2 * q);                     \
        float partial[8];                                                   \
        gates_partial<13>(w1t, 1326, va, va + 1, partial);                  \
        float h = lstm_update(partial, bias1, mask, s, cc1);                \
        sm[v1ow + wp_ * 208] = h;                                           \
        sm[v2in] = h;                                                       \
    }                                                                       \
} while (0)

#define PHASE2(tv) do {                                                     \
    int rp_ = (tv) & 1, wp_ = 1 - rp_;                                      \
    if (local < 204) {                                                      \
        const ulonglong2* va = s ? (gvu + 320 + rp_ * 52 + 2 * q)           \
                                 : (gvu + 268 + 2 * q);                     \
        float partial[8];                                                   \
        gates_partial<13>(w2t, 1326, va, va + 1, partial);                  \
        float h = lstm_update(partial, bias2, mask, s, cc2);                \
        sm[v2ow + wp_ * 208] = h;                                           \
    }                                                                       \
} while (0)

    NB();   // x(0) visible to group before first phase0

    if (grp == 0) {
        for (int t = 0; t < TT; ++t) {
            PHASE0(t); NB();
            PHASE1(t); NB();
            PHASE2(t); NB();
        }
    } else {
        PHASE0(0); NB();
        for (int t = 0; t < TT; ++t) {
            PHASE1(t); NB();
            PHASE2(t); NB();
            if (t + 1 < TT) PHASE0(t + 1);
            NB();
        }
    }

    // final head: outputs for t = TT-1 (h2 in own buffer parity TT&1 = 0)
    if (local >= 204 && local < 212) {
        int idx = local - 204, hb = idx >> 1, col = idx & 1;
        float acc = sm[14338 * 4 + col];
        const float* h2 = sm + GVf + 1280 + (TT & 1) * 208;
#pragma unroll 1
        for (int kk = 0; kk < 51; ++kk)
            acc += sm[14312 * 4 + col * 52 + kk]
                 * h2[((kk >> 2) * 4 + hb) * 4 + (kk & 3)];
        if (col) acc = (acc > 30.f) ? acc : log1pf(__expf(acc));
        out[((gb0 + grp * 4 + hb) * TT + (TT - 1)) * 2 + col] = acc;
    }
}

extern "C" void kernel_launch(void* const* d_in, const int* in_sizes, int n_in,
                              void* d_out, int out_size)
{
    static bool attr_set = false;
    if (!attr_set) {
        cudaFuncSetAttribute(lstm_kernel,
                             cudaFuncAttributeMaxDynamicSharedMemorySize, SMEM_BYTES);
        attr_set = true;
    }
    lstm_kernel<<<NCTA, NTH, SMEM_BYTES>>>(
        (const float*)d_in[0],  (const float*)d_in[1],
        (const float*)d_in[2],  (const float*)d_in[3],
        (const float*)d_in[4],  (const float*)d_in[5],
        (const float*)d_in[6],  (const float*)d_in[7],
        (const float*)d_in[8],  (const float*)d_in[9],
        (const float*)d_in[10], (const float*)d_in[11],
        (const float*)d_in[12], (const float*)d_in[13],
        (const float*)d_in[14], (const float*)d_in[15],
        (float*)d_out);
}

// round 11
// speedup vs baseline: 1.0560x; 1.0560x over previous
#include <cuda_runtime.h>

#define TT   2048
#define NCTA 128
#define NTH  512

typedef unsigned long long ull;

__device__ __forceinline__ float losum(ull v) {
    float lo, hi; asm("mov.b64 {%0,%1}, %2;" : "=f"(lo), "=f"(hi) : "l"(v));
    return lo + hi;
}
__device__ __forceinline__ ull ff2(ull a, ull b, ull c) {
    ull d; asm("fma.rn.f32x2 %0, %1, %2, %3;" : "=l"(d) : "l"(a), "l"(b), "l"(c));
    return d;
}
__device__ __forceinline__ ull add2(ull a, ull b) {
    ull d; asm("add.rn.f32x2 %0, %1, %2;" : "=l"(d) : "l"(a), "l"(b));
    return d;
}
__device__ __forceinline__ float ex2f(float x){ float y; asm("ex2.approx.f32 %0, %1;" : "=f"(y) : "f"(x)); return y; }
__device__ __forceinline__ float rcpf(float x){ float y; asm("rcp.approx.f32 %0, %1;" : "=f"(y) : "f"(x)); return y; }
__device__ __forceinline__ float sigm(float x){ return rcpf(1.f + ex2f(-1.4426950408889634f * x)); }
__device__ __forceinline__ float tanh_(float x){ float e = ex2f(2.8853900817779268f * x); return 1.f - 2.f * rcpf(e + 1.f); }

// Partial dot, 4 gates x 2 batches over J float4-chunks (this thread's K-half).
// v j-stride = 4 u2 (4 batches per group); w j-stride = 51 u2.
template<int J>
__device__ __forceinline__ void gates_partial(
    const ulonglong2* __restrict__ wt, int gstr,
    const ulonglong2* __restrict__ va, const ulonglong2* __restrict__ vb,
    float* __restrict__ partial)
{
    ull ax[4], ay[4], bx[4], by[4];
#pragma unroll
    for (int g = 0; g < 4; ++g) { ax[g] = 0ULL; ay[g] = 0ULL; bx[g] = 0ULL; by[g] = 0ULL; }
#pragma unroll
    for (int j = 0; j < J; ++j) {
        const ulonglong2 ha = va[j * 4];
        const ulonglong2 hb = vb[j * 4];
#pragma unroll
        for (int g = 0; g < 4; ++g) {
            const ulonglong2 wv = wt[g * gstr + j * 51];
            ax[g] = ff2(wv.x, ha.x, ax[g]);
            ay[g] = ff2(wv.y, ha.y, ay[g]);
            bx[g] = ff2(wv.x, hb.x, bx[g]);
            by[g] = ff2(wv.y, hb.y, by[g]);
        }
    }
#pragma unroll
    for (int g = 0; g < 4; ++g) {
        partial[g * 2 + 0] = losum(add2(ax[g], ay[g]));
        partial[g * 2 + 1] = losum(add2(bx[g], by[g]));
    }
}

__device__ __forceinline__ float lstm_update(const float* __restrict__ partial,
                                             const float* __restrict__ bias4,
                                             unsigned mask, int s, float& cc)
{
    float full[4];
#pragma unroll
    for (int g = 0; g < 4; ++g) {
        float prov = s ? partial[g * 2 + 0] : partial[g * 2 + 1];
        float recv = __shfl_xor_sync(mask, prov, 1);
        float mine = s ? partial[g * 2 + 1] : partial[g * 2 + 0];
        full[g] = mine + recv + bias4[g];
    }
    float gi = sigm(full[0]), gf = sigm(full[1]);
    float gg = tanh_(full[2]), go = sigm(full[3]);
    cc = gf * cc + gi * gg;
    return go * tanh_(cc);
}

// ---- smem map (u2 = 16B units) ----
// W0: [g][s][j<7][k<51]  : 8*357  = 2856 u2 @ 0
// W1: [g][s][j<13][k<51] : 8*663  = 5304 u2 @ 2856
// W2:                      5304 u2 @ 8160
// V (per group, 424 u2)  @ 13464 + grp*424:
//   v0: 2 bufs x 56   (cols: x0,x1,h0(51),pad3; [j][b])
//   v1: in 52 | own 2 x 52
//   v2: in 52 | own 2 x 52
// WL @ 14312 (26 u2), BL @ 14338 (1 u2)
#define SMEM_BYTES (14340 * 16)

__global__ void __launch_bounds__(NTH, 1)
lstm_kernel(const float* __restrict__ inp,  const float* __restrict__ tim,
            const float* __restrict__ Wih0, const float* __restrict__ Whh0,
            const float* __restrict__ bih0, const float* __restrict__ bhh0,
            const float* __restrict__ Wih1, const float* __restrict__ Whh1,
            const float* __restrict__ bih1, const float* __restrict__ bhh1,
            const float* __restrict__ Wih2, const float* __restrict__ Whh2,
            const float* __restrict__ bih2, const float* __restrict__ bhh2,
            const float* __restrict__ Wlin, const float* __restrict__ blin,
            float* __restrict__ out)
{
    extern __shared__ float sm[];
    ulonglong2* smu2 = (ulonglong2*)sm;
    const int tid = threadIdx.x;
    const int gb0 = blockIdx.x * 8;

    // ---- init (all 512 threads) ----
    for (int i = tid; i < 2856 * 4; i += NTH) {           // W0
        int u = i >> 2, e = i & 3;
        int gs = u / 357, rem = u - gs * 357;
        int j = rem / 51, kk = rem - j * 51;
        int g = gs >> 1, s = gs & 1;
        int c = s * 28 + j * 4 + e;
        int r = g * 51 + kk;
        float v = 0.f;
        if (c < 2)       v = Wih0[r * 2 + c];
        else if (c < 53) v = Whh0[r * 51 + (c - 2)];
        sm[i] = v;
    }
    for (int i = tid; i < 5304 * 4; i += NTH) {           // W1, W2
        int u = i >> 2, e = i & 3;
        int gs = u / 663, rem = u - gs * 663;
        int j = rem / 51, kk = rem - j * 51;
        int g = gs >> 1, s = gs & 1;
        int c = s * 52 + j * 4 + e;
        int r = g * 51 + kk;
        float v1 = 0.f, v2 = 0.f;
        if (c < 51)                  { v1 = Wih1[r * 51 + c];        v2 = Wih2[r * 51 + c]; }
        else if (c >= 52 && c < 103) { v1 = Whh1[r * 51 + (c - 52)]; v2 = Whh2[r * 51 + (c - 52)]; }
        sm[2856 * 4 + i] = v1;
        sm[8160 * 4 + i] = v2;
    }
    for (int i = tid; i < 848 * 4; i += NTH) sm[13464 * 4 + i] = 0.f;   // v regions
    for (int i = tid; i < 104; i += NTH) {
        int col = i / 52, kk = i - col * 52;
        sm[14312 * 4 + i] = (kk < 51) ? Wlin[col * 51 + kk] : 0.f;
    }
    if (tid < 2) sm[14338 * 4 + tid] = blin[tid];
    __syncthreads();

    const int grp = tid >> 8;            // 0 / 1
    const int local = tid & 255;
    if ((local >> 5) == 7) return;       // warps 7,15 exit after init

    const int GVf = (13464 + grp * 424) * 4;
    const ulonglong2* gvu = smu2 + 13464 + grp * 424;
    const int bid = grp + 1;             // named barrier id

    // x(t=0) into v0 buffer 0
    if (local >= 212 && local < 220) {
        int idx = local - 212, xb = idx & 3, xsel = idx >> 2;
        const float* src = xsel ? tim : inp;
        sm[GVf + xb * 4 + xsel] = src[(gb0 + grp * 4 + xb) * TT];
    }

    // gemv roles (valid for local < 204)
    const int s = local & 1;
    const int q = (local >> 1) & 1;
    const int k = local >> 2;
    const int b = 2 * q + s;
    const unsigned mask = (local < 192) ? 0xFFFFFFFFu : 0x00000FFFu;

    float bias0[4], bias1[4], bias2[4];
    if (local < 204) {
#pragma unroll
        for (int g = 0; g < 4; ++g) {
            int r = g * 51 + k;
            bias0[g] = bih0[r] + bhh0[r];
            bias1[g] = bih1[r] + bhh1[r];
            bias2[g] = bih2[r] + bhh2[r];
        }
    }
    const ulonglong2* w0t = smu2 + 0    + s * 357 + k;
    const ulonglong2* w1t = smu2 + 2856 + s * 663 + k;
    const ulonglong2* w2t = smu2 + 8160 + s * 663 + k;

    const int c0 = 2 + k;
    const int h0st = GVf + (((c0 >> 2) * 4 + b) * 4) + (c0 & 3);          // + wp*224
    const int kst  = (((k >> 2) * 4 + b) * 4) + (k & 3);
    const int v1in = GVf + 448  + kst;
    const int v1ow = GVf + 656  + kst;                                     // + wp*208
    const int v2in = GVf + 1072 + kst;
    const int v2ow = GVf + 1280 + kst;                                     // + wp*208

    float cc0 = 0.f, cc1 = 0.f, cc2 = 0.f;

#define NB() asm volatile("bar.sync %0, %1;" :: "r"(bid), "r"(224) : "memory")

#define PHASE0(tv) do {                                                     \
    int rp_ = (tv) & 1, wp_ = 1 - rp_;                                      \
    if (local < 204) {                                                      \
        const ulonglong2* va = gvu + rp_ * 56 + s * 28 + 2 * q;             \
        float partial[8];                                                   \
        gates_partial<7>(w0t, 714, va, va + 1, partial);                    \
        float h = lstm_update(partial, bias0, mask, s, cc0);                \
        sm[h0st + wp_ * 224] = h;                                           \
        sm[v1in] = h;                                                       \
    } else if (local < 212) {                                               \
        if ((tv) > 0) {                                                     \
            int idx = local - 204, hb = idx >> 1, col = idx & 1;            \
            float acc = sm[14338 * 4 + col];                                \
            const float* h2 = sm + GVf + 1280 + rp_ * 208;                  \
            _Pragma("unroll 1")                                             \
            for (int kk = 0; kk < 51; ++kk)                                 \
                acc += sm[14312 * 4 + col * 52 + kk]                        \
                     * h2[((kk >> 2) * 4 + hb) * 4 + (kk & 3)];             \
            if (col) acc = (acc > 30.f) ? acc : log1pf(__expf(acc));        \
            out[((gb0 + grp * 4 + hb) * TT + ((tv) - 1)) * 2 + col] = acc;  \
        }                                                                   \
    } else if (local < 220) {                                               \
        if ((tv) + 1 < TT) {                                                \
            int idx = local - 212, xb = idx & 3, xsel = idx >> 2;           \
            const float* src = xsel ? tim : inp;                            \
            float xin = src[(gb0 + grp * 4 + xb) * TT + ((tv) + 1)];        \
            sm[GVf + wp_ * 224 + xb * 4 + xsel] = xin;                      \
        }                                                                   \
    }                                                                       \
} while (0)

#define PHASE1(tv) do {                                                     \
    int rp_ = (tv) & 1, wp_ = 1 - rp_;                                      \
    if (local < 204) {                                                      \
        const ulonglong2* va = s ? (gvu + 164 + rp_ * 52 + 2 * q)           \
                                 : (gvu + 112 + 2 * q);                     \
        float partial[8];                                                   \
        gates_partial<13>(w1t, 1326, va, va + 1, partial);                  \
        float h = lstm_update(partial, bias1, mask, s, cc1);                \
        sm[v1ow + wp_ * 208] = h;                                           \
        sm[v2in] = h;                                                       \
    }                                                                       \
} while (0)

#define PHASE2(tv) do {                                                     \
    int rp_ = (tv) & 1, wp_ = 1 - rp_;                                      \
    if (local < 204) {                                                      \
        const ulonglong2* va = s ? (gvu + 320 + rp_ * 52 + 2 * q)           \
                                 : (gvu + 268 + 2 * q);                     \
        float partial[8];                                                   \
        gates_partial<13>(w2t, 1326, va, va + 1, partial);                  \
        float h = lstm_update(partial, bias2, mask, s, cc2);                \
        sm[v2ow + wp_ * 208] = h;                                           \
    }                                                                       \
} while (0)

    NB();   // x(0) visible to group before first phase0

    if (grp == 0) {
        for (int t = 0; t < TT; ++t) {
            PHASE0(t); NB();
            PHASE1(t); NB();
            PHASE2(t); NB();
        }
    } else {
        PHASE0(0); NB();
        for (int t = 0; t < TT; ++t) {
            PHASE1(t); NB();
            PHASE2(t); NB();
            if (t + 1 < TT) PHASE0(t + 1);
            NB();
        }
    }

    // final head: outputs for t = TT-1 (h2 in own buffer parity TT&1 = 0)
    if (local >= 204 && local < 212) {
        int idx = local - 204, hb = idx >> 1, col = idx & 1;
        float acc = sm[14338 * 4 + col];
        const float* h2 = sm + GVf + 1280 + (TT & 1) * 208;
#pragma unroll 1
        for (int kk = 0; kk < 51; ++kk)
            acc += sm[14312 * 4 + col * 52 + kk]
                 * h2[((kk >> 2) * 4 + hb) * 4 + (kk & 3)];
        if (col) acc = (acc > 30.f) ? acc : log1pf(__expf(acc));
        out[((gb0 + grp * 4 + hb) * TT + (TT - 1)) * 2 + col] = acc;
    }
}

extern "C" void kernel_launch(void* const* d_in, const int* in_sizes, int n_in,
                              void* d_out, int out_size)
{
    static bool attr_set = false;
    if (!attr_set) {
        cudaFuncSetAttribute(lstm_kernel,
                             cudaFuncAttributeMaxDynamicSharedMemorySize, SMEM_BYTES);
        attr_set = true;
    }
    lstm_kernel<<<NCTA, NTH, SMEM_BYTES>>>(
        (const float*)d_in[0],  (const float*)d_in[1],
        (const float*)d_in[2],  (const float*)d_in[3],
        (const float*)d_in[4],  (const float*)d_in[5],
        (const float*)d_in[6],  (const float*)d_in[7],
        (const float*)d_in[8],  (const float*)d_in[9],
        (const float*)d_in[10], (const float*)d_in[11],
        (const float*)d_in[12], (const float*)d_in[13],
        (const float*)d_in[14], (const float*)d_in[15],
        (float*)d_out);
}

// round 12
// speedup vs baseline: 1.3477x; 1.2762x over previous
#include <cuda_runtime.h>
#define TT 2048
#define NCTA 128
#define NTH 256
typedef unsigned long long ull;

__device__ __forceinline__ float losum(ull v){ float lo,hi; asm("mov.b64 {%0,%1}, %2;":"=f"(lo),"=f"(hi):"l"(v)); return lo+hi; }
__device__ __forceinline__ ull ff2(ull a,ull b,ull c){ ull d; asm("fma.rn.f32x2 %0, %1, %2, %3;":"=l"(d):"l"(a),"l"(b),"l"(c)); return d; }
__device__ __forceinline__ float ex2f(float x){ float y; asm("ex2.approx.f32 %0, %1;":"=f"(y):"f"(x)); return y; }
__device__ __forceinline__ float rcpf(float x){ float y; asm("rcp.approx.f32 %0, %1;":"=f"(y):"f"(x)); return y; }
__device__ __forceinline__ float sigm(float x){ return rcpf(1.f+ex2f(-1.4426950408889634f*x)); }
__device__ __forceinline__ float tanh_(float x){ float e=ex2f(2.8853900817779268f*x); return 1.f-2.f*rcpf(e+1.f); }

// L1/L2 body: 4 gates x 8 batches over this thread's K-quarter, butterfly-reduce
// over the 4 sq lanes, update c, emit h for batches 2*sq+{0,1}.
__device__ __forceinline__ void l12(
    const ulonglong2* __restrict__ wq, const ulonglong2* __restrict__ vp,
    int nj7, const float* __restrict__ b4, unsigned mask, int s0, int s1,
    float* __restrict__ cc, float* __restrict__ hout)
{
    ull ac[4][8];
#pragma unroll
    for (int g=0; g<4; ++g)
#pragma unroll
        for (int b=0; b<8; ++b) ac[g][b]=0ULL;
#pragma unroll
    for (int jj=0; jj<7; ++jj) {
        if (jj==6 && !nj7) break;
        ulonglong2 w0=wq[jj*51], w1=wq[jj*51+1326], w2=wq[jj*51+2652], w3=wq[jj*51+3978];
#pragma unroll
        for (int b=0; b<8; ++b) {
            ulonglong2 hv=vp[jj*9+b];
            ac[0][b]=ff2(w0.x,hv.x,ac[0][b]); ac[0][b]=ff2(w0.y,hv.y,ac[0][b]);
            ac[1][b]=ff2(w1.x,hv.x,ac[1][b]); ac[1][b]=ff2(w1.y,hv.y,ac[1][b]);
            ac[2][b]=ff2(w2.x,hv.x,ac[2][b]); ac[2][b]=ff2(w2.y,hv.y,ac[2][b]);
            ac[3][b]=ff2(w3.x,hv.x,ac[3][b]); ac[3][b]=ff2(w3.y,hv.y,ac[3][b]);
        }
    }
    float q[4][4];
#pragma unroll
    for (int g=0; g<4; ++g)
#pragma unroll
        for (int i=0; i<4; ++i) {
            int m=i>>1, e=i&1;
            float av=losum(ac[g][4*m+e]), bv=losum(ac[g][4*m+e+2]);
            float send=s0?av:bv, keep=s0?bv:av;
            q[g][i]=keep+__shfl_xor_sync(mask,send,1);
        }
#pragma unroll
    for (int e=0; e<2; ++e) {
        float r[4];
#pragma unroll
        for (int g=0; g<4; ++g) {
            float av=q[g][e], bv=q[g][2+e];
            float send=s1?av:bv, keep=s1?bv:av;
            r[g]=keep+__shfl_xor_sync(mask,send,2)+b4[g];
        }
        float gi=sigm(r[0]), gf=sigm(r[1]), gg=tanh_(r[2]), go=sigm(r[3]);
        cc[e]=gf*cc[e]+gi*gg;
        hout[e]=go*tanh_(cc[e]);
    }
}

// smem (u2 units): W0@0 [g][j<14][k] 2856 | W1@2856 [g][ch<26][k] 5304 | W2@8160 5304
// V0@13464 2x126 | V1IN@13716 117 | V1OW@13833 2x117 | V2IN@14067 117 | V2OW@14184 2x117
// WL@14418 26 | BL@14444
#define SMEM_BYTES (14445*16)

__global__ void __launch_bounds__(NTH,1)
lstm_kernel(const float* __restrict__ inp, const float* __restrict__ tim,
            const float* __restrict__ Wih0,const float* __restrict__ Whh0,
            const float* __restrict__ bih0,const float* __restrict__ bhh0,
            const float* __restrict__ Wih1,const float* __restrict__ Whh1,
            const float* __restrict__ bih1,const float* __restrict__ bhh1,
            const float* __restrict__ Wih2,const float* __restrict__ Whh2,
            const float* __restrict__ bih2,const float* __restrict__ bhh2,
            const float* __restrict__ Wlin,const float* __restrict__ blin,
            float* __restrict__ out)
{
    extern __shared__ float sm[];
    ulonglong2* su=(ulonglong2*)sm;
    const int tid=threadIdx.x;
    const int gb0=blockIdx.x*8;

    for (int i=tid; i<2856*4; i+=NTH) {                 // W0
        int u=i>>2, e=i&3, g=u/714, rem=u-g*714, j=rem/51, kk=rem-j*51;
        int c=j*4+e, r=g*51+kk; float v=0.f;
        if (c<2) v=Wih0[r*2+c]; else if (c<53) v=Whh0[r*51+(c-2)];
        sm[i]=v;
    }
    for (int i=tid; i<5304*4; i+=NTH) {                 // W1,W2
        int u=i>>2, e=i&3, g=u/1326, rem=u-g*1326, ch=rem/51, kk=rem-ch*51;
        int c=ch*4+e, r=g*51+kk; float v1=0.f, v2=0.f;
        if (c<51) { v1=Wih1[r*51+c]; v2=Wih2[r*51+c]; }
        else if (c>=52 && c<103) { v1=Whh1[r*51+(c-52)]; v2=Whh2[r*51+(c-52)]; }
        sm[2856*4+i]=v1; sm[8160*4+i]=v2;
    }
    for (int i=tid; i<(14418-13464)*4; i+=NTH) sm[13464*4+i]=0.f;
    for (int i=tid; i<104; i+=NTH) {
        int col=i/52, kk=i-col*52;
        sm[14418*4+i]=(kk<51)?Wlin[col*51+kk]:0.f;
    }
    if (tid<2) sm[14444*4+tid]=blin[tid];
    __syncthreads();
    if (tid>=240) {                                     // x(t=0)
        int idx=tid-240, xb=idx&7, sel=idx>>3;
        const float* src=sel?tim:inp;
        sm[(13464+xb)*4+sel]=src[(gb0+xb)*TT];
    }

    const int k=tid>>2, sq=tid&3, s0=sq&1, s1=sq>>1;
    const bool comp=(tid<204);
    const unsigned mask=(tid<192)?0xFFFFFFFFu:0x00000FFFu;

    float b0g[4],b1g[4],b2g[4];
    if (comp) {
#pragma unroll
        for (int g=0; g<4; ++g) {
            int r=g*51+k;
            b0g[g]=bih0[r]+bhh0[r]; b1g[g]=bih1[r]+bhh1[r]; b2g[g]=bih2[r]+bhh2[r];
        }
    }
    const int ofs=s1*663+s0*357;
    const ulonglong2* w0p=su+k;
    const ulonglong2* w1p=su+2856+ofs+k;
    const ulonglong2* w2p=su+8160+ofs+k;
    const int nj7=(s0==0);

    int v1base[2], v2base[2];
    if (!s1) { v1base[0]=v1base[1]=13716+s0*63; v2base[0]=v2base[1]=14067+s0*63; }
    else     { v1base[0]=13833+s0*63; v1base[1]=13833+117+s0*63;
               v2base[0]=14184+s0*63; v2base[1]=14184+117+s0*63; }

    const int c0=2+k;
    const int stv0  =(13464+(c0>>2)*9+2*sq)*4+(c0&3);      // +wp*504 +e*4
    const int kj    =(k>>2)*9+2*sq;
    const int stv1in=(13716+kj)*4+(k&3);
    const int stv1ow=(13833+kj)*4+(k&3);                   // +wp*468 +e*4
    const int stv2in=(14067+kj)*4+(k&3);
    const int stv2ow=(14184+kj)*4+(k&3);                   // +wp*468 +e*4

    float cc0[2]={0.f,0.f}, cc1[2]={0.f,0.f}, cc2[2]={0.f,0.f};
    __syncthreads();

    for (int t=0; t<TT; ++t) {
        const int rp=t&1, wp=1-rp;
        // ---- phase 0: L0 full-K, 2 batches | head(t-1) | x(t+1) ----
        if (comp) {
            ull a0[4][2];
#pragma unroll
            for (int g=0; g<4; ++g) { a0[g][0]=0ULL; a0[g][1]=0ULL; }
            const ulonglong2* vp=su+13464+rp*126+2*sq;
#pragma unroll
            for (int jj=0; jj<14; ++jj) {
                ulonglong2 hva=vp[jj*9], hvb=vp[jj*9+1];
#pragma unroll
                for (int g=0; g<4; ++g) {
                    ulonglong2 wv=w0p[(g*14+jj)*51];
                    a0[g][0]=ff2(wv.x,hva.x,a0[g][0]); a0[g][0]=ff2(wv.y,hva.y,a0[g][0]);
                    a0[g][1]=ff2(wv.x,hvb.x,a0[g][1]); a0[g][1]=ff2(wv.y,hvb.y,a0[g][1]);
                }
            }
#pragma unroll
            for (int e=0; e<2; ++e) {
                float gi=sigm(losum(a0[0][e])+b0g[0]);
                float gf=sigm(losum(a0[1][e])+b0g[1]);
                float gg=tanh_(losum(a0[2][e])+b0g[2]);
                float go=sigm(losum(a0[3][e])+b0g[3]);
                cc0[e]=gf*cc0[e]+gi*gg;
                float h=go*tanh_(cc0[e]);
                sm[stv0+wp*504+e*4]=h;
                sm[stv1in+e*4]=h;
            }
        } else if (tid>=224) {
            int lane=tid-224;
            if (lane>=16) {
                if (t+1<TT) {
                    int idx=lane-16, xb=idx&7, sel=idx>>3;
                    const float* src=sel?tim:inp;
                    sm[(13464+wp*126+xb)*4+sel]=src[(gb0+xb)*TT+t+1];
                }
            } else if (t>0) {
                int hb=lane>>1, col=lane&1;
                float acc=sm[14444*4+col];
                const int hbase=(14184+rp*117)*4;
#pragma unroll 1
                for (int kk=0; kk<51; ++kk)
                    acc+=sm[14418*4+col*52+kk]*sm[hbase+((kk>>2)*9+hb)*4+(kk&3)];
                if (col) acc=(acc>30.f)?acc:log1pf(__expf(acc));
                out[((gb0+hb)*TT+(t-1))*2+col]=acc;
            }
        }
        __syncthreads();
        // ---- phase 1: L1 ----
        if (comp) {
            float h[2];
            l12(w1p, su+v1base[rp], nj7, b1g, mask, s0, s1, cc1, h);
            sm[stv1ow+wp*468]=h[0]; sm[stv1ow+wp*468+4]=h[1];
            sm[stv2in]=h[0];        sm[stv2in+4]=h[1];
        }
        __syncthreads();
        // ---- phase 2: L2 ----
        if (comp) {
            float h[2];
            l12(w2p, su+v2base[rp], nj7, b2g, mask, s0, s1, cc2, h);
            sm[stv2ow+wp*468]=h[0]; sm[stv2ow+wp*468+4]=h[1];
        }
        __syncthreads();
    }
    // final head t=TT-1: h2 in buffer (TT&1)=0
    if (tid>=224 && tid<240) {
        int lane=tid-224, hb=lane>>1, col=lane&1;
        float acc=sm[14444*4+col];
        const int hbase=(14184+(TT&1)*117)*4;
#pragma unroll 1
        for (int kk=0; kk<51; ++kk)
            acc+=sm[14418*4+col*52+kk]*sm[hbase+((kk>>2)*9+hb)*4+(kk&3)];
        if (col) acc=(acc>30.f)?acc:log1pf(__expf(acc));
        out[((gb0+hb)*TT+(TT-1))*2+col]=acc;
    }
}

extern "C" void kernel_launch(void* const* d_in, const int* in_sizes, int n_in,
                              void* d_out, int out_size)
{
    static bool attr_set=false;
    if (!attr_set) {
        cudaFuncSetAttribute(lstm_kernel, cudaFuncAttributeMaxDynamicSharedMemorySize, SMEM_BYTES);
        attr_set=true;
    }
    lstm_kernel<<<NCTA, NTH, SMEM_BYTES>>>(
        (const float*)d_in[0],  (const float*)d_in[1],
        (const float*)d_in[2],  (const float*)d_in[3],
        (const float*)d_in[4],  (const float*)d_in[5],
        (const float*)d_in[6],  (const float*)d_in[7],
        (const float*)d_in[8],  (const float*)d_in[9],
        (const float*)d_in[10], (const float*)d_in[11],
        (const float*)d_in[12], (const float*)d_in[13],
        (const float*)d_in[14], (const float*)d_in[15],
        (float*)d_out);
}